// round 4
// baseline (speedup 1.0000x reference)
#include <cuda_runtime.h>
#include <cstdint>

#define BATCH 8192
#define DIMN  4096
#define HIDN  256
#define NHEAD 16
#define SEQL  2048

// Static scratch (allocation-free). All K-axes stored in "fragment order":
// within each 16-float K group, position p holds logical k where
// p = ((k&3)<<2) | ((k>>2)&3)  (4x4 transpose, self-inverse).
__device__ float g_hidden[(size_t)BATCH * DIMN];   // tf32-rounded, K-permuted
__device__ float g_xr[(size_t)BATCH * DIMN];       // tf32-rounded, K-permuted
__device__ float g_bt1[(size_t)DIMN * DIMN];       // W_proj^T [(h*256+n)][k], rounded, K-permuted
__device__ float g_bt2[(size_t)DIMN * DIMN];       // W_out^T  [n][k], rounded, K-permuted

__device__ __forceinline__ float rna_tf32(float x) {
    float r;
    asm("cvt.rna.tf32.f32 %0, %1;" : "=f"(r) : "f"(x));
    return r;
}
__device__ __forceinline__ uint32_t smem_u32(const void* p) {
    uint32_t a;
    asm("{ .reg .u64 t; cvta.to.shared.u64 t, %1; cvt.u32.u64 %0, t; }"
        : "=r"(a) : "l"(p));
    return a;
}
__device__ __forceinline__ void lds128(uint32_t* v, uint32_t addr) {
    asm volatile("ld.shared.v4.b32 {%0,%1,%2,%3}, [%4];"
                 : "=r"(v[0]), "=r"(v[1]), "=r"(v[2]), "=r"(v[3]) : "r"(addr));
}

// ---------------------------------------------------------------------------
// Pre-pass kernels
// ---------------------------------------------------------------------------
// round + permute: each thread handles one 16-float group (4x4 reg transpose)
__global__ void round_perm_kernel(const float4* __restrict__ src,
                                  float4* __restrict__ dst, int ngroups) {
    int gi = blockIdx.x * blockDim.x + threadIdx.x;
    if (gi >= ngroups) return;
    float4 i0 = src[gi * 4 + 0], i1 = src[gi * 4 + 1];
    float4 i2 = src[gi * 4 + 2], i3 = src[gi * 4 + 3];
    float4 o0 = { rna_tf32(i0.x), rna_tf32(i1.x), rna_tf32(i2.x), rna_tf32(i3.x) };
    float4 o1 = { rna_tf32(i0.y), rna_tf32(i1.y), rna_tf32(i2.y), rna_tf32(i3.y) };
    float4 o2 = { rna_tf32(i0.z), rna_tf32(i1.z), rna_tf32(i2.z), rna_tf32(i3.z) };
    float4 o3 = { rna_tf32(i0.w), rna_tf32(i1.w), rna_tf32(i2.w), rna_tf32(i3.w) };
    dst[gi * 4 + 0] = o0; dst[gi * 4 + 1] = o1;
    dst[gi * 4 + 2] = o2; dst[gi * 4 + 3] = o3;
}

// transpose + round + permute-K.  src: batch b of [R][C] row-major.
// dst[(b*C + c)][perm(r)] = rna(src[r][c]),  dst K-major with ld = R.
__global__ void transpose_round_kernel(const float* __restrict__ src,
                                       float* __restrict__ dst, int R, int C) {
    __shared__ float tile[32][33];
    const int b = blockIdx.z;
    const float* s = src + (size_t)b * R * C;
    const int c0 = blockIdx.x * 32, r0 = blockIdx.y * 32;
    const int tx = threadIdx.x, ty = threadIdx.y;
    #pragma unroll
    for (int j = 0; j < 4; j++)
        tile[ty + 8 * j][tx] = rna_tf32(s[(size_t)(r0 + ty + 8 * j) * C + c0 + tx]);
    __syncthreads();
    // permuted K position for logical column r0+tx
    const int pc = r0 + ((tx & ~15) | ((tx & 3) << 2) | ((tx >> 2) & 3));
    #pragma unroll
    for (int j = 0; j < 4; j++)
        dst[(size_t)(b * C + c0 + ty + 8 * j) * R + pc] = tile[tx][ty + 8 * j];
}

// ---------------------------------------------------------------------------
// tf32 mma.sync GEMM. CTA 128(M) x 256(N) x 32(K), 3-stage cp.async,
// 8 warps (2M x 4N), warp tile 64x64, all fragment loads LDS.128.
// A [M,K] row-major (K-permuted), B [N,K] n-major (K-permuted).
// MODE 1: C = rna( w*(acc+b_proj) + coef*cache + b_mix ), stored K-permuted
// MODE 2: C = acc + b_out   (plain layout)
// ---------------------------------------------------------------------------
template <int MODE>
__global__ __launch_bounds__(256, 1)
void gemm_tf32mma(const float* __restrict__ A, const float* __restrict__ B,
                  float* __restrict__ C,
                  const float* __restrict__ b_proj, const float* __restrict__ w_mix,
                  const float* __restrict__ b_mix, const float* __restrict__ decay_values,
                  const float* __restrict__ caches, const int* __restrict__ index_p,
                  const float* __restrict__ b_out)
{
    constexpr int BK = 32;
    constexpr int NS = 3;
    constexpr int NT = DIMN / BK;                  // 128 k-slabs
    constexpr int A_BYTES = 128 * BK * 4;          // 16 KB
    constexpr int B_BYTES = 256 * BK * 4;          // 32 KB
    constexpr int STAGE_BYTES = A_BYTES + B_BYTES; // 48 KB

    extern __shared__ float smem[];
    const uint32_t smem0 = smem_u32(smem);

    const int tid  = threadIdx.x;
    const int wid  = tid >> 5;
    const int lane = tid & 31;
    const int warpM = wid & 1;    // 0..1  (64 rows)
    const int warpN = wid >> 1;   // 0..3  (64 cols)
    const int grp = lane >> 2;    // 0..7
    const int tig = lane & 3;     // 0..3

    const int row0 = blockIdx.y * 128;
    const int n0   = blockIdx.x * 256;
    const float* aBase = A + (size_t)row0 * DIMN;
    const float* bBase = B + (size_t)n0 * DIMN;

    auto load = [&](int s, int kt) {
        const uint32_t sA = smem0 + s * STAGE_BYTES;
        const uint32_t sB = sA + A_BYTES;
        #pragma unroll
        for (int i = 0; i < 4; i++) {              // A: 1024 16B chunks
            const int g = tid + i * 256;
            const int r = g >> 3, ch = g & 7;
            const uint32_t dst = sA + (uint32_t)(r * 128 + ((ch ^ (r & 7)) << 4));
            asm volatile("cp.async.cg.shared.global [%0], [%1], 16;"
                         :: "r"(dst), "l"(aBase + (size_t)r * DIMN + kt + ch * 4));
        }
        #pragma unroll
        for (int i = 0; i < 8; i++) {              // B: 2048 16B chunks
            const int g = tid + i * 256;
            const int r = g >> 3, ch = g & 7;
            const uint32_t dst = sB + (uint32_t)(r * 128 + ((ch ^ (r & 7)) << 4));
            asm volatile("cp.async.cg.shared.global [%0], [%1], 16;"
                         :: "r"(dst), "l"(bBase + (size_t)r * DIMN + kt + ch * 4));
        }
        asm volatile("cp.async.commit_group;");
    };

    float acc[4][8][4];
    #pragma unroll
    for (int mi = 0; mi < 4; mi++)
        #pragma unroll
        for (int ni = 0; ni < 8; ni++)
            #pragma unroll
            for (int v = 0; v < 4; v++) acc[mi][ni][v] = 0.0f;

    load(0, 0);
    load(1, BK);

    for (int t = 0; t < NT; t++) {
        if (t < NT - 1) asm volatile("cp.async.wait_group 1;" ::: "memory");
        else            asm volatile("cp.async.wait_group 0;" ::: "memory");
        __syncthreads();

        if (t + 2 < NT) load((t + 2) % NS, (t + 2) * BK);

        const uint32_t stA = smem0 + (t % NS) * STAGE_BYTES;
        const uint32_t stB = stA + A_BYTES;

        #pragma unroll
        for (int g = 0; g < 2; g++) {
            // A fragments: 8 LDS.128  (covers ki = 2g and 2g+1)
            uint32_t af[4][2][4];
            #pragma unroll
            for (int mi = 0; mi < 4; mi++)
                #pragma unroll
                for (int rh = 0; rh < 2; rh++) {
                    const int r = warpM * 64 + mi * 16 + rh * 8 + grp;
                    lds128(af[mi][rh],
                           stA + (uint32_t)(r * 128 + (((g * 4 + tig) ^ (r & 7)) << 4)));
                }
            // B fragments: 8 LDS.128
            uint32_t bf[8][4];
            #pragma unroll
            for (int ni = 0; ni < 8; ni++) {
                const int nr = warpN * 64 + ni * 8 + grp;
                lds128(bf[ni],
                       stB + (uint32_t)(nr * 128 + (((g * 4 + tig) ^ (nr & 7)) << 4)));
            }
            #pragma unroll
            for (int s = 0; s < 2; s++)
                #pragma unroll
                for (int mi = 0; mi < 4; mi++)
                    #pragma unroll
                    for (int ni = 0; ni < 8; ni++)
                        asm volatile(
                            "mma.sync.aligned.m16n8k8.row.col.f32.tf32.tf32.f32 "
                            "{%0,%1,%2,%3}, {%4,%5,%6,%7}, {%8,%9}, {%0,%1,%2,%3};"
                            : "+f"(acc[mi][ni][0]), "+f"(acc[mi][ni][1]),
                              "+f"(acc[mi][ni][2]), "+f"(acc[mi][ni][3])
                            : "r"(af[mi][0][2 * s]), "r"(af[mi][1][2 * s]),
                              "r"(af[mi][0][2 * s + 1]), "r"(af[mi][1][2 * s + 1]),
                              "r"(bf[ni][2 * s]), "r"(bf[ni][2 * s + 1]));
        }
    }

    // ------------------------------ epilogue ------------------------------
    if (MODE == 1) {
        const int h = blockIdx.x;            // BN = 256 = one full head
        const int idx = *index_p;
        float dv = fminf(fmaxf(decay_values[h], 0.9f), 1.0f);
        const float decay = sqrtf(sqrtf(dv));
        const float w  = w_mix[(size_t)h * SEQL + idx];
        const float bb = b_mix[(size_t)h * SEQL + idx];
        const float coef = (h < NHEAD / 2) ? (w * decay) : decay;

        #pragma unroll
        for (int mi = 0; mi < 4; mi++) {
            #pragma unroll
            for (int rh = 0; rh < 2; rh++) {
                const int r = row0 + warpM * 64 + mi * 16 + rh * 8 + grp;
                const float* cacheRow = caches + ((size_t)h * BATCH + r) * HIDN;
                float* Crow = C + (size_t)r * DIMN + n0;
                #pragma unroll
                for (int ni = 0; ni < 8; ni++) {
                    #pragma unroll
                    for (int e = 0; e < 2; e++) {
                        const int cc = warpN * 64 + ni * 8 + 2 * tig + e;
                        float v = w * (acc[mi][ni][rh * 2 + e] + b_proj[h * HIDN + cc])
                                + coef * cacheRow[cc] + bb;
                        const int pcc = (cc & ~15) | ((cc & 3) << 2) | ((cc >> 2) & 3);
                        Crow[pcc] = rna_tf32(v);
                    }
                }
            }
        }
    } else {
        #pragma unroll
        for (int mi = 0; mi < 4; mi++) {
            #pragma unroll
            for (int rh = 0; rh < 2; rh++) {
                const int r = row0 + warpM * 64 + mi * 16 + rh * 8 + grp;
                float* Crow = C + (size_t)r * DIMN + n0;
                #pragma unroll
                for (int ni = 0; ni < 8; ni++) {
                    const int cc = warpN * 64 + ni * 8 + 2 * tig;
                    float2 v;
                    v.x = acc[mi][ni][rh * 2 + 0] + b_out[n0 + cc];
                    v.y = acc[mi][ni][rh * 2 + 1] + b_out[n0 + cc + 1];
                    *reinterpret_cast<float2*>(Crow + cc) = v;
                }
            }
        }
    }
}

// ---------------------------------------------------------------------------
extern "C" void kernel_launch(void* const* d_in, const int* in_sizes, int n_in,
                              void* d_out, int out_size)
{
    const float* x       = (const float*)d_in[0];
    const int*   index_p = (const int*)  d_in[1];
    const float* W_proj  = (const float*)d_in[2];
    const float* b_proj  = (const float*)d_in[3];
    const float* W_out   = (const float*)d_in[4];
    const float* b_out   = (const float*)d_in[5];
    const float* w_mix   = (const float*)d_in[6];
    const float* b_mix   = (const float*)d_in[7];
    const float* decay   = (const float*)d_in[8];
    const float* caches  = (const float*)d_in[9];
    float* out = (float*)d_out;

    float *hidden, *xr, *bt1, *bt2;
    cudaGetSymbolAddress((void**)&hidden, g_hidden);
    cudaGetSymbolAddress((void**)&xr,     g_xr);
    cudaGetSymbolAddress((void**)&bt1,    g_bt1);
    cudaGetSymbolAddress((void**)&bt2,    g_bt2);

    const int SMEM_DYN = 3 * (128 + 256) * 32 * 4;   // 144 KB
    cudaFuncSetAttribute(gemm_tf32mma<1>, cudaFuncAttributeMaxDynamicSharedMemorySize, SMEM_DYN);
    cudaFuncSetAttribute(gemm_tf32mma<2>, cudaFuncAttributeMaxDynamicSharedMemorySize, SMEM_DYN);

    {
        const int ng = (BATCH * DIMN) / 16;
        round_perm_kernel<<<(ng + 255) / 256, 256>>>((const float4*)x, (float4*)xr, ng);
    }
    transpose_round_kernel<<<dim3(HIDN / 32, DIMN / 32, NHEAD), dim3(32, 8)>>>(
        W_proj, bt1, DIMN, HIDN);
    transpose_round_kernel<<<dim3(DIMN / 32, DIMN / 32, 1), dim3(32, 8)>>>(
        W_out, bt2, DIMN, DIMN);

    dim3 grid(DIMN / 256, BATCH / 128);   // 16 x 64
    gemm_tf32mma<1><<<grid, 256, SMEM_DYN>>>(xr, bt1, hidden,
                                             b_proj, w_mix, b_mix, decay, caches,
                                             index_p, b_out);
    gemm_tf32mma<2><<<grid, 256, SMEM_DYN>>>(hidden, bt2, out,
                                             b_proj, w_mix, b_mix, decay, caches,
                                             index_p, b_out);
}

// round 7
// speedup vs baseline: 1.1148x; 1.1148x over previous
#include <cuda_runtime.h>
#include <cstdint>

#define BATCH 8192
#define DIMN  4096
#define HIDN  256
#define NHEAD 16
#define SEQL  2048

// Static scratch (allocation-free). All K-axes stored in "fragment order":
// within each 16-float K group, position p holds logical k where
// p = ((k&3)<<2) | ((k>>2)&3)  (4x4 transpose, self-inverse).
__device__ float g_hidden[(size_t)BATCH * DIMN];   // tf32-rounded, K-permuted
__device__ float g_xr[(size_t)BATCH * DIMN];       // tf32-rounded, K-permuted
__device__ float g_bt1[(size_t)DIMN * DIMN];       // W_proj^T [(h*256+n)][k], rounded, K-permuted
__device__ float g_bt2[(size_t)DIMN * DIMN];       // W_out^T  [n][k], rounded, K-permuted

__device__ __forceinline__ float rna_tf32(float x) {
    float r;
    asm("cvt.rna.tf32.f32 %0, %1;" : "=f"(r) : "f"(x));
    return r;
}
__device__ __forceinline__ uint32_t smem_u32(const void* p) {
    uint32_t a;
    asm("{ .reg .u64 t; cvta.to.shared.u64 t, %1; cvt.u32.u64 %0, t; }"
        : "=r"(a) : "l"(p));
    return a;
}
__device__ __forceinline__ void lds128(uint32_t* v, uint32_t addr) {
    asm volatile("ld.shared.v4.b32 {%0,%1,%2,%3}, [%4];"
                 : "=r"(v[0]), "=r"(v[1]), "=r"(v[2]), "=r"(v[3]) : "r"(addr));
}

// ---------------------------------------------------------------------------
// Pre-pass kernels
// ---------------------------------------------------------------------------
__global__ void round_perm_kernel(const float4* __restrict__ src,
                                  float4* __restrict__ dst, int ngroups) {
    int gi = blockIdx.x * blockDim.x + threadIdx.x;
    if (gi >= ngroups) return;
    float4 i0 = src[gi * 4 + 0], i1 = src[gi * 4 + 1];
    float4 i2 = src[gi * 4 + 2], i3 = src[gi * 4 + 3];
    float4 o0 = { rna_tf32(i0.x), rna_tf32(i1.x), rna_tf32(i2.x), rna_tf32(i3.x) };
    float4 o1 = { rna_tf32(i0.y), rna_tf32(i1.y), rna_tf32(i2.y), rna_tf32(i3.y) };
    float4 o2 = { rna_tf32(i0.z), rna_tf32(i1.z), rna_tf32(i2.z), rna_tf32(i3.z) };
    float4 o3 = { rna_tf32(i0.w), rna_tf32(i1.w), rna_tf32(i2.w), rna_tf32(i3.w) };
    dst[gi * 4 + 0] = o0; dst[gi * 4 + 1] = o1;
    dst[gi * 4 + 2] = o2; dst[gi * 4 + 3] = o3;
}

// transpose + round + permute-K.  src: batch b of [R][C] row-major.
// dst[(b*C + c)][perm(r)] = rna(src[r][c]),  dst K-major with ld = R.
__global__ void transpose_round_kernel(const float* __restrict__ src,
                                       float* __restrict__ dst, int R, int C) {
    __shared__ float tile[32][33];
    const int b = blockIdx.z;
    const float* s = src + (size_t)b * R * C;
    const int c0 = blockIdx.x * 32, r0 = blockIdx.y * 32;
    const int tx = threadIdx.x, ty = threadIdx.y;
    #pragma unroll
    for (int j = 0; j < 4; j++)
        tile[ty + 8 * j][tx] = rna_tf32(s[(size_t)(r0 + ty + 8 * j) * C + c0 + tx]);
    __syncthreads();
    const int pc = r0 + ((tx & ~15) | ((tx & 3) << 2) | ((tx >> 2) & 3));
    #pragma unroll
    for (int j = 0; j < 4; j++)
        dst[(size_t)(b * C + c0 + ty + 8 * j) * R + pc] = tile[tx][ty + 8 * j];
}

// ---------------------------------------------------------------------------
// tf32 mma.sync GEMM. CTA 128(M) x 128(N) x 32(K), 3-stage cp.async,
// 4 warps (2M x 2N), warp tile 64x64, all fragment loads LDS.128,
// 96 KB SMEM -> 2 CTAs/SM (independent barriers hide sync shadows).
// A [M,K] row-major (K-permuted), B [N,K] n-major (K-permuted).
// MODE 1: C = rna( w*(acc+b_proj) + coef*cache + b_mix ), stored K-permuted
// MODE 2: C = acc + b_out   (plain layout)
// ---------------------------------------------------------------------------
template <int MODE>
__global__ __launch_bounds__(128, 2)
void gemm_tf32mma(const float* __restrict__ A, const float* __restrict__ B,
                  float* __restrict__ C,
                  const float* __restrict__ b_proj, const float* __restrict__ w_mix,
                  const float* __restrict__ b_mix, const float* __restrict__ decay_values,
                  const float* __restrict__ caches, const int* __restrict__ index_p,
                  const float* __restrict__ b_out)
{
    constexpr int BK = 32;
    constexpr int NT = DIMN / BK;                  // 128 k-slabs
    constexpr int A_BYTES = 128 * BK * 4;          // 16 KB
    constexpr int B_BYTES = 128 * BK * 4;          // 16 KB
    constexpr int STAGE_BYTES = A_BYTES + B_BYTES; // 32 KB

    extern __shared__ float smem[];
    const uint32_t smem0 = smem_u32(smem);

    const int tid  = threadIdx.x;
    const int wid  = tid >> 5;
    const int lane = tid & 31;
    const int warpM = wid & 1;    // 0..1  (64 rows)
    const int warpN = wid >> 1;   // 0..1  (64 cols)
    const int grp = lane >> 2;    // 0..7
    const int tig = lane & 3;     // 0..3

    const int row0 = blockIdx.y * 128;
    const int n0   = blockIdx.x * 128;
    const float* aBase = A + (size_t)row0 * DIMN;
    const float* bBase = B + (size_t)n0 * DIMN;

    auto load = [&](int s, int kt) {
        const uint32_t sA = smem0 + s * STAGE_BYTES;
        const uint32_t sB = sA + A_BYTES;
        #pragma unroll
        for (int i = 0; i < 8; i++) {              // A: 1024 16B chunks / 128 thr
            const int g = tid + i * 128;
            const int r = g >> 3, ch = g & 7;
            const uint32_t sw = (uint32_t)(r * 128 + ((ch ^ (r & 7)) << 4));
            asm volatile("cp.async.cg.shared.global [%0], [%1], 16;"
                         :: "r"(sA + sw), "l"(aBase + (size_t)r * DIMN + kt + ch * 4));
            asm volatile("cp.async.cg.shared.global [%0], [%1], 16;"
                         :: "r"(sB + sw), "l"(bBase + (size_t)r * DIMN + kt + ch * 4));
        }
        asm volatile("cp.async.commit_group;");
    };

    float acc[4][8][4];
    #pragma unroll
    for (int mi = 0; mi < 4; mi++)
        #pragma unroll
        for (int ni = 0; ni < 8; ni++)
            #pragma unroll
            for (int v = 0; v < 4; v++) acc[mi][ni][v] = 0.0f;

    load(0, 0);
    load(1, BK);

    int s_cur = 0, s_pre = 2;
    for (int t = 0; t < NT; t++) {
        if (t < NT - 1) asm volatile("cp.async.wait_group 1;" ::: "memory");
        else            asm volatile("cp.async.wait_group 0;" ::: "memory");
        __syncthreads();

        if (t + 2 < NT) load(s_pre, (t + 2) * BK);

        const uint32_t stA = smem0 + s_cur * STAGE_BYTES;
        const uint32_t stB = stA + A_BYTES;
        s_cur = (s_cur == 2) ? 0 : s_cur + 1;
        s_pre = (s_pre == 2) ? 0 : s_pre + 1;

        #pragma unroll
        for (int g = 0; g < 2; g++) {
            uint32_t af[4][2][4];
            #pragma unroll
            for (int mi = 0; mi < 4; mi++)
                #pragma unroll
                for (int rh = 0; rh < 2; rh++) {
                    const int r = warpM * 64 + mi * 16 + rh * 8 + grp;
                    lds128(af[mi][rh],
                           stA + (uint32_t)(r * 128 + (((g * 4 + tig) ^ (r & 7)) << 4)));
                }
            uint32_t bf[8][4];
            #pragma unroll
            for (int ni = 0; ni < 8; ni++) {
                const int nr = warpN * 64 + ni * 8 + grp;
                lds128(bf[ni],
                       stB + (uint32_t)(nr * 128 + (((g * 4 + tig) ^ (nr & 7)) << 4)));
            }
            #pragma unroll
            for (int s = 0; s < 2; s++)
                #pragma unroll
                for (int mi = 0; mi < 4; mi++)
                    #pragma unroll
                    for (int ni = 0; ni < 8; ni++)
                        asm volatile(
                            "mma.sync.aligned.m16n8k8.row.col.f32.tf32.tf32.f32 "
                            "{%0,%1,%2,%3}, {%4,%5,%6,%7}, {%8,%9}, {%0,%1,%2,%3};"
                            : "+f"(acc[mi][ni][0]), "+f"(acc[mi][ni][1]),
                              "+f"(acc[mi][ni][2]), "+f"(acc[mi][ni][3])
                            : "r"(af[mi][0][2 * s]), "r"(af[mi][1][2 * s]),
                              "r"(af[mi][0][2 * s + 1]), "r"(af[mi][1][2 * s + 1]),
                              "r"(bf[ni][2 * s]), "r"(bf[ni][2 * s + 1]));
        }
    }

    // ------------------------------ epilogue ------------------------------
    if (MODE == 1) {
        const int h  = blockIdx.x >> 1;          // BN=128: two CTAs per head
        const int k0 = (blockIdx.x & 1) * 128;
        const int idx = *index_p;
        float dv = fminf(fmaxf(decay_values[h], 0.9f), 1.0f);
        const float decay = sqrtf(sqrtf(dv));
        const float w  = w_mix[(size_t)h * SEQL + idx];
        const float bb = b_mix[(size_t)h * SEQL + idx];
        const float coef = (h < NHEAD / 2) ? (w * decay) : decay;

        #pragma unroll
        for (int mi = 0; mi < 4; mi++) {
            #pragma unroll
            for (int rh = 0; rh < 2; rh++) {
                const int r = row0 + warpM * 64 + mi * 16 + rh * 8 + grp;
                const float* cacheRow = caches + ((size_t)h * BATCH + r) * HIDN;
                float* Crow = C + (size_t)r * DIMN + n0;
                #pragma unroll
                for (int ni = 0; ni < 8; ni++) {
                    #pragma unroll
                    for (int e = 0; e < 2; e++) {
                        const int cc = warpN * 64 + ni * 8 + 2 * tig + e;  // 0..127
                        const int k  = k0 + cc;                            // 0..255
                        float v = w * (acc[mi][ni][rh * 2 + e] + b_proj[h * HIDN + k])
                                + coef * cacheRow[k] + bb;
                        const int pcc = (cc & ~15) | ((cc & 3) << 2) | ((cc >> 2) & 3);
                        Crow[pcc] = rna_tf32(v);
                    }
                }
            }
        }
    } else {
        #pragma unroll
        for (int mi = 0; mi < 4; mi++) {
            #pragma unroll
            for (int rh = 0; rh < 2; rh++) {
                const int r = row0 + warpM * 64 + mi * 16 + rh * 8 + grp;
                float* Crow = C + (size_t)r * DIMN + n0;
                #pragma unroll
                for (int ni = 0; ni < 8; ni++) {
                    const int cc = warpN * 64 + ni * 8 + 2 * tig;
                    float2 v;
                    v.x = acc[mi][ni][rh * 2 + 0] + b_out[n0 + cc];
                    v.y = acc[mi][ni][rh * 2 + 1] + b_out[n0 + cc + 1];
                    *reinterpret_cast<float2*>(Crow + cc) = v;
                }
            }
        }
    }
}

// ---------------------------------------------------------------------------
extern "C" void kernel_launch(void* const* d_in, const int* in_sizes, int n_in,
                              void* d_out, int out_size)
{
    const float* x       = (const float*)d_in[0];
    const int*   index_p = (const int*)  d_in[1];
    const float* W_proj  = (const float*)d_in[2];
    const float* b_proj  = (const float*)d_in[3];
    const float* W_out   = (const float*)d_in[4];
    const float* b_out   = (const float*)d_in[5];
    const float* w_mix   = (const float*)d_in[6];
    const float* b_mix   = (const float*)d_in[7];
    const float* decay   = (const float*)d_in[8];
    const float* caches  = (const float*)d_in[9];
    float* out = (float*)d_out;

    float *hidden, *xr, *bt1, *bt2;
    cudaGetSymbolAddress((void**)&hidden, g_hidden);
    cudaGetSymbolAddress((void**)&xr,     g_xr);
    cudaGetSymbolAddress((void**)&bt1,    g_bt1);
    cudaGetSymbolAddress((void**)&bt2,    g_bt2);

    const int SMEM_DYN = 3 * (128 + 128) * 32 * 4;   // 96 KB
    cudaFuncSetAttribute(gemm_tf32mma<1>, cudaFuncAttributeMaxDynamicSharedMemorySize, SMEM_DYN);
    cudaFuncSetAttribute(gemm_tf32mma<2>, cudaFuncAttributeMaxDynamicSharedMemorySize, SMEM_DYN);

    {
        const int ng = (BATCH * DIMN) / 16;
        round_perm_kernel<<<(ng + 255) / 256, 256>>>((const float4*)x, (float4*)xr, ng);
    }
    transpose_round_kernel<<<dim3(HIDN / 32, DIMN / 32, NHEAD), dim3(32, 8)>>>(
        W_proj, bt1, DIMN, HIDN);
    transpose_round_kernel<<<dim3(DIMN / 32, DIMN / 32, 1), dim3(32, 8)>>>(
        W_out, bt2, DIMN, DIMN);

    dim3 grid(DIMN / 128, BATCH / 128);   // 32 x 64
    gemm_tf32mma<1><<<grid, 128, SMEM_DYN>>>(xr, bt1, hidden,
                                             b_proj, w_mix, b_mix, decay, caches,
                                             index_p, b_out);
    gemm_tf32mma<2><<<grid, 128, SMEM_DYN>>>(hidden, bt2, out,
                                             b_proj, w_mix, b_mix, decay, caches,
                                             index_p, b_out);
}